// round 8
// baseline (speedup 1.0000x reference)
#include <cuda_runtime.h>
#include <cstdint>
#include <cstddef>

#define A_DIM 64
#define B_DIM 256
#define D_DIM 128
#define H_DIM 512
#define G4    2048
#define NCTA  64
#define TPB   256
#define NCOLS 256

// ---------------- device scratch (static: no allocations allowed) ----------------
__device__ float g_pre_enc[A_DIM * G4];                       // 512 KB (transposed gate layout)
__device__ float g_pre_dec[(size_t)NCOLS * A_DIM * G4];       // 134 MB (transposed gate layout)
// h exchange: [parity][replica][cta] -> one private 128B line, words 0..7 = h[8*cta .. 8*cta+7]
__device__ __align__(128) float g_hp[2][4][NCTA][32];
// 8 split barrier counters, each on its own 128B line
__device__ __align__(128) unsigned int g_ctr8[8 * 32];
__device__ float g_outs[NCOLS * D_DIM];                       // per-column projections

// gate column remap: old g = type*512 + j  ->  new col = (j>>3)*32 + (j&7)*4 + type
__host__ __device__ __forceinline__ int inv_gate_map(int ng)
{
    const int type = ng & 3;
    const int w    = (ng >> 2) & 7;
    const int cta  = ng >> 5;
    return type * H_DIM + cta * 8 + w;   // old row index into Wih/bias
}

// ---------------- pre-activation GEMM (writes transposed gate layout) ----------------
#define BM 64
#define BN 64
#define BK 64

__global__ void pre_gemm_kernel(const float* __restrict__ x,
                                const float* __restrict__ Wih,
                                const float* __restrict__ bih,
                                const float* __restrict__ bhh,
                                int dec)
{
    __shared__ float Xs[BM][BK + 1];
    __shared__ float Ws[BN][BK + 1];
    float* __restrict__ outp = dec ? g_pre_dec : g_pre_enc;

    const int m0 = blockIdx.x * BM;
    const int n0 = blockIdx.y * BN;
    const int tid = threadIdx.x;
    const int tx = tid & 15;
    const int ty = tid >> 4;

    float acc[4][4];
#pragma unroll
    for (int r = 0; r < 4; r++)
#pragma unroll
        for (int c = 0; c < 4; c++) acc[r][c] = 0.f;

    const int lr = tid >> 2;         // 0..63
    const int lc = (tid & 3) * 16;   // 0,16,32,48

#pragma unroll
    for (int kit = 0; kit < 2; kit++) {
        const int k0 = kit * BK;
        {
            const int m = m0 + lr;
            const float* src;
            if (dec) {
                const int i = m >> 6;       // column index
                const int t = m & 63;       // timestep
                src = x + ((size_t)(t * B_DIM + (B_DIM - 1 - i))) * D_DIM + k0 + lc;
            } else {
                src = x + ((size_t)(m * B_DIM + (B_DIM - 1))) * D_DIM + k0 + lc;
            }
#pragma unroll
            for (int q = 0; q < 4; q++) {
                float4 v = *(const float4*)(src + q * 4);
                Xs[lr][lc + q * 4 + 0] = v.x;
                Xs[lr][lc + q * 4 + 1] = v.y;
                Xs[lr][lc + q * 4 + 2] = v.z;
                Xs[lr][lc + q * 4 + 3] = v.w;
            }
        }
        {
            // W tile rows gathered through the inverse gate map (rows stay coalesced)
            const int og = inv_gate_map(n0 + lr);
            const float* src = Wih + (size_t)og * D_DIM + k0 + lc;
#pragma unroll
            for (int q = 0; q < 4; q++) {
                float4 v = *(const float4*)(src + q * 4);
                Ws[lr][lc + q * 4 + 0] = v.x;
                Ws[lr][lc + q * 4 + 1] = v.y;
                Ws[lr][lc + q * 4 + 2] = v.z;
                Ws[lr][lc + q * 4 + 3] = v.w;
            }
        }
        __syncthreads();
#pragma unroll 16
        for (int kk = 0; kk < BK; kk++) {
            float a[4], bb[4];
#pragma unroll
            for (int r = 0; r < 4; r++) a[r] = Xs[ty * 4 + r][kk];
#pragma unroll
            for (int c = 0; c < 4; c++) bb[c] = Ws[tx * 4 + c][kk];
#pragma unroll
            for (int r = 0; r < 4; r++)
#pragma unroll
                for (int c = 0; c < 4; c++) acc[r][c] = fmaf(a[r], bb[c], acc[r][c]);
        }
        __syncthreads();
    }
#pragma unroll
    for (int r = 0; r < 4; r++) {
        const int m = m0 + ty * 4 + r;
#pragma unroll
        for (int c = 0; c < 4; c++) {
            const int ng = n0 + tx * 4 + c;
            const int og = inv_gate_map(ng);
            outp[(size_t)m * G4 + ng] = acc[r][c] + bih[og] + bhh[og];
        }
    }
}

// ---------------- init (runs every launch) ----------------
__global__ void init_kernel()
{
    const int t = blockIdx.x * blockDim.x + threadIdx.x;
    if (t < 2 * 4 * NCTA * 32) ((float*)g_hp)[t] = 0.f;
    if (t < 8 * 32) g_ctr8[t] = 0u;
}

// ---------------- fast math helpers ----------------
__device__ __forceinline__ float tanh_fast(float x)
{
    float y;
    asm("tanh.approx.f32 %0, %1;" : "=f"(y) : "f"(x));
    return y;
}
__device__ __forceinline__ float sigm(float x)
{
    return fmaf(tanh_fast(0.5f * x), 0.5f, 0.5f);
}
__device__ __forceinline__ unsigned long long fma2(unsigned long long a,
                                                   unsigned long long b,
                                                   unsigned long long c)
{
    unsigned long long d;
    asm("fma.rn.f32x2 %0, %1, %2, %3;" : "=l"(d) : "l"(a), "l"(b), "l"(c));
    return d;
}
__device__ __forceinline__ unsigned long long add2(unsigned long long a,
                                                   unsigned long long b)
{
    unsigned long long d;
    asm("add.rn.f32x2 %0, %1, %2;" : "=l"(d) : "l"(a), "l"(b));
    return d;
}
__device__ __forceinline__ unsigned long long pack2(float lo, float hi)
{
    return ((unsigned long long)__float_as_uint(hi) << 32) | (unsigned long long)__float_as_uint(lo);
}

__device__ __forceinline__ const float* pre_row(unsigned u)
{
    return (u < A_DIM) ? (g_pre_enc + (size_t)u * G4)
                       : (g_pre_dec + (size_t)(u - A_DIM) * G4);
}

// ---------------- sequential recurrent kernel ----------------
__global__ void __launch_bounds__(TPB, 1) lstm_seq_kernel(
    const float* __restrict__ enc_Whh,
    const float* __restrict__ dec_Whh,
    const float* __restrict__ lin_W,
    const float* __restrict__ lin_b)
{
    __shared__ float s_h[544];   // padded h: idx(k) = k + 2*(k>>5)
    __shared__ float s_red[8];   // projection partials

    const int b    = blockIdx.x;
    const int tid  = threadIdx.x;
    const int wid  = tid >> 5;               // warp = local hidden unit 0..7
    const int lane = tid & 31;
    const int gate = lane >> 3;              // 0..3 = i,f,g,o
    const int q    = lane & 7;               // k-partition (64 wide)
    const int jg   = b * 8 + wid;            // global hidden unit
    const int grow = gate * H_DIM + jg;      // row of Whh

    // persistent recurrent weights as packed f32x2 (64 floats per thread per LSTM)
    unsigned long long we2[32], wd2[32];
    {
        const float2* se = (const float2*)(enc_Whh + (size_t)grow * H_DIM + 64 * q);
        const float2* sd = (const float2*)(dec_Whh + (size_t)grow * H_DIM + 64 * q);
#pragma unroll
        for (int t = 0; t < 32; t++) { float2 v = se[t]; we2[t] = pack2(v.x, v.y); }
#pragma unroll
        for (int t = 0; t < 32; t++) { float2 v = sd[t]; wd2[t] = pack2(v.x, v.y); }
    }
    // projection weights: thread covers 4 h of output dim d = 2b + (tid>>7)
    const int kk = tid & 127;
    const int dd = 2 * b + (tid >> 7);
    const float4 lwv = __ldg((const float4*)(lin_W + (size_t)dd * H_DIM + 4 * kk));
    const float  lbv = __ldg(lin_b + dd);

    float c_reg = 0.f;
    unsigned bar = 0;
    int buf = 0;
    float4 pre_next = __ldg((const float4*)(pre_row(0) + (b << 5) + (wid << 2)));
    __syncthreads();

    // read 512-wide h (parity buf, replica b&3) into padded SMEM; even tids stage
    auto stage = [&]() {
        if (!(tid & 1)) {
            const int sidx = tid >> 1;   // 0..127
            const float4 hv = __ldcg((const float4*)&g_hp[buf][b & 3][sidx >> 1][(sidx & 1) << 2]);
            const int base = 4 * sidx + 2 * (sidx >> 3);
            s_h[base + 0] = hv.x;
            s_h[base + 1] = hv.y;
            s_h[base + 2] = hv.z;
            s_h[base + 3] = hv.w;
        }
        __syncthreads();
    };

    auto step = [&](const unsigned long long (&w2)[32], unsigned u) {
        const float4 pcur = pre_next;
        pre_next = __ldg((const float4*)(pre_row(u + 1) + (b << 5) + (wid << 2)));
        stage();
        // dot over k = 64q .. 64q+63 with packed f32x2 FMAs (4 chains)
        const unsigned long long* h_lo = (const unsigned long long*)(s_h + 68 * q);
        const unsigned long long* h_hi = (const unsigned long long*)(s_h + 68 * q + 34);
        unsigned long long a0 = 0ull, a1 = 0ull, a2 = 0ull, a3 = 0ull;
#pragma unroll
        for (int t = 0; t < 16; t += 4) {
            a0 = fma2(w2[t + 0], h_lo[t + 0], a0);
            a1 = fma2(w2[t + 1], h_lo[t + 1], a1);
            a2 = fma2(w2[t + 2], h_lo[t + 2], a2);
            a3 = fma2(w2[t + 3], h_lo[t + 3], a3);
        }
#pragma unroll
        for (int t = 0; t < 16; t += 4) {
            a0 = fma2(w2[16 + t + 0], h_hi[t + 0], a0);
            a1 = fma2(w2[16 + t + 1], h_hi[t + 1], a1);
            a2 = fma2(w2[16 + t + 2], h_hi[t + 2], a2);
            a3 = fma2(w2[16 + t + 3], h_hi[t + 3], a3);
        }
        const unsigned long long at = add2(add2(a0, a1), add2(a2, a3));
        float sum = __uint_as_float((unsigned)at) + __uint_as_float((unsigned)(at >> 32));
        // all-reduce within each 8-lane gate group
        sum += __shfl_xor_sync(0xffffffffu, sum, 1);
        sum += __shfl_xor_sync(0xffffffffu, sum, 2);
        sum += __shfl_xor_sync(0xffffffffu, sum, 4);
        // gather the four gate sums to lane 0
        const float vi = __shfl_sync(0xffffffffu, sum, 0);
        const float vf = __shfl_sync(0xffffffffu, sum, 8);
        const float vg = __shfl_sync(0xffffffffu, sum, 16);
        const float vo = __shfl_sync(0xffffffffu, sum, 24);
        if (lane == 0) {
            const float gi = vi + pcur.x;
            const float gf = vf + pcur.y;
            const float gg = vg + pcur.z;
            const float go = vo + pcur.w;
            const float cn = fmaf(sigm(gf), c_reg, sigm(gi) * tanh_fast(gg));
            const float hn = sigm(go) * tanh_fast(cn);
            c_reg = cn;
#pragma unroll
            for (int r = 0; r < 4; r++) g_hp[buf ^ 1][r][b][wid] = hn;   // 4 replicas
            __threadfence();
        }
        __syncthreads();          // all warps' h stores + s_h reads complete
        bar++;
        if (tid == 0) {
            asm volatile("red.release.gpu.global.add.u32 [%0], 1;"
                         :: "l"(g_ctr8 + ((b >> 3) << 5)) : "memory");
        }
        if (tid < 8) {
            const unsigned tgt = bar * 8u;   // 8 CTAs per counter
            const unsigned int* cp = g_ctr8 + (tid << 5);
            unsigned v;
            do {
                asm volatile("ld.acquire.gpu.global.u32 %0, [%1];"
                             : "=r"(v) : "l"(cp) : "memory");
            } while (v < tgt);
        }
        __syncthreads();
        buf ^= 1;
    };

    auto proj = [&](int i) {
        stage();
        const int base = 4 * kk + 2 * (kk >> 3);
        const float2 h01 = *(const float2*)(s_h + base);
        const float2 h23 = *(const float2*)(s_h + base + 2);
        float v = fmaf(lwv.x, h01.x, lwv.y * h01.y) + fmaf(lwv.z, h23.x, lwv.w * h23.y);
#pragma unroll
        for (int m = 16; m >= 1; m >>= 1) v += __shfl_xor_sync(0xffffffffu, v, m);
        if (lane == 0) s_red[wid] = v;
        __syncthreads();
        if (tid == 0)
            g_outs[(NCOLS - 1 - i) * D_DIM + 2 * b] =
                lbv + s_red[0] + s_red[1] + s_red[2] + s_red[3];
        if (tid == 128)
            g_outs[(NCOLS - 1 - i) * D_DIM + 2 * b + 1] =
                lbv + s_red[4] + s_red[5] + s_red[6] + s_red[7];
    };

    unsigned u = 0;
    // ---- encoder: 64 steps on batch row 255 only ----
    for (int t = 0; t < A_DIM; t++) step(we2, u++);
    // ---- decoder: 256 columns; projection first, then 64 steps (last column dead) ----
    for (int i = 0; i < NCOLS; i++) {
        proj(i);
        if (i < NCOLS - 1)
            for (int t = 0; t < A_DIM; t++) step(wd2, u++);
    }
}

// ---------------- broadcast outs (256x128) over leading A dim -> (64,256,128) ----------------
__global__ void bcast_kernel(float* __restrict__ out)
{
    const unsigned idx = blockIdx.x * blockDim.x + threadIdx.x;
    out[idx] = g_outs[idx & (NCOLS * D_DIM - 1)];
}

// ---------------- launch ----------------
extern "C" void kernel_launch(void* const* d_in, const int* in_sizes, int n_in,
                              void* d_out, int out_size)
{
    const float* x       = (const float*)d_in[0];
    const float* enc_Wih = (const float*)d_in[1];
    const float* enc_Whh = (const float*)d_in[2];
    const float* enc_bih = (const float*)d_in[3];
    const float* enc_bhh = (const float*)d_in[4];
    const float* dec_Wih = (const float*)d_in[5];
    const float* dec_Whh = (const float*)d_in[6];
    const float* dec_bih = (const float*)d_in[7];
    const float* dec_bhh = (const float*)d_in[8];
    const float* lin_W   = (const float*)d_in[9];
    const float* lin_b   = (const float*)d_in[10];
    float* out = (float*)d_out;

    // pre-activations (parallel, off the critical chain)
    pre_gemm_kernel<<<dim3(1, G4 / BN), TPB>>>(x, enc_Wih, enc_bih, enc_bhh, 0);
    pre_gemm_kernel<<<dim3((NCOLS * A_DIM) / BM, G4 / BN), TPB>>>(x, dec_Wih, dec_bih, dec_bhh, 1);

    // reset h lines + counters every launch (graph replays)
    init_kernel<<<64, 256>>>();

    // sequential recurrent chain: 16384 steps, persistent 64-CTA grid
    lstm_seq_kernel<<<NCTA, TPB>>>(enc_Whh, dec_Whh, lin_W, lin_b);

    // broadcast to (64, 256, 128)
    bcast_kernel<<<(64u * 256u * 128u) / 256u, 256u>>>(out);
}

// round 10
// speedup vs baseline: 1.6945x; 1.6945x over previous
#include <cuda_runtime.h>
#include <cstdint>
#include <cstddef>

#define A_DIM 64
#define B_DIM 256
#define D_DIM 128
#define H_DIM 512
#define G4    2048
#define NCTA  128
#define TPB   256
#define NCOLS 256

// ---------------- device scratch (static: no allocations allowed) ----------------
__device__ float g_pre_enc[A_DIM * G4];                       // transposed gate layout
__device__ float g_pre_dec[(size_t)NCOLS * A_DIM * G4];       // transposed gate layout
// h exchange: [parity][replica][cta] -> private 128B line, words 0..3 = h[4*cta .. 4*cta+3]
__device__ __align__(128) float g_hp[2][4][NCTA][32];
// 8 split barrier counters, each on its own 128B line
__device__ __align__(128) unsigned int g_ctr8[8 * 32];
__device__ float g_outs[NCOLS * D_DIM];                       // per-column projections

// new gate column ng = cta*16 + wid*4 + gate  ->  old row = gate*512 + cta*4 + wid
__host__ __device__ __forceinline__ int inv_gate_map(int ng)
{
    const int gate = ng & 3;
    const int w    = (ng >> 2) & 3;
    const int cta  = ng >> 4;
    return gate * H_DIM + cta * 4 + w;
}

// ---------------- pre-activation GEMM (writes transposed gate layout) ----------------
#define BM 64
#define BN 64
#define BK 64

__global__ void pre_gemm_kernel(const float* __restrict__ x,
                                const float* __restrict__ Wih,
                                const float* __restrict__ bih,
                                const float* __restrict__ bhh,
                                int dec)
{
    __shared__ float Xs[BM][BK + 1];
    __shared__ float Ws[BN][BK + 1];
    float* __restrict__ outp = dec ? g_pre_dec : g_pre_enc;

    const int m0 = blockIdx.x * BM;
    const int n0 = blockIdx.y * BN;
    const int tid = threadIdx.x;
    const int tx = tid & 15;
    const int ty = tid >> 4;

    float acc[4][4];
#pragma unroll
    for (int r = 0; r < 4; r++)
#pragma unroll
        for (int c = 0; c < 4; c++) acc[r][c] = 0.f;

    const int lr = tid >> 2;
    const int lc = (tid & 3) * 16;

#pragma unroll
    for (int kit = 0; kit < 2; kit++) {
        const int k0 = kit * BK;
        {
            const int m = m0 + lr;
            const float* src;
            if (dec) {
                const int i = m >> 6;
                const int t = m & 63;
                src = x + ((size_t)(t * B_DIM + (B_DIM - 1 - i))) * D_DIM + k0 + lc;
            } else {
                src = x + ((size_t)(m * B_DIM + (B_DIM - 1))) * D_DIM + k0 + lc;
            }
#pragma unroll
            for (int q = 0; q < 4; q++) {
                float4 v = *(const float4*)(src + q * 4);
                Xs[lr][lc + q * 4 + 0] = v.x;
                Xs[lr][lc + q * 4 + 1] = v.y;
                Xs[lr][lc + q * 4 + 2] = v.z;
                Xs[lr][lc + q * 4 + 3] = v.w;
            }
        }
        {
            const int og = inv_gate_map(n0 + lr);
            const float* src = Wih + (size_t)og * D_DIM + k0 + lc;
#pragma unroll
            for (int q = 0; q < 4; q++) {
                float4 v = *(const float4*)(src + q * 4);
                Ws[lr][lc + q * 4 + 0] = v.x;
                Ws[lr][lc + q * 4 + 1] = v.y;
                Ws[lr][lc + q * 4 + 2] = v.z;
                Ws[lr][lc + q * 4 + 3] = v.w;
            }
        }
        __syncthreads();
#pragma unroll 16
        for (int kk = 0; kk < BK; kk++) {
            float a[4], bb[4];
#pragma unroll
            for (int r = 0; r < 4; r++) a[r] = Xs[ty * 4 + r][kk];
#pragma unroll
            for (int c = 0; c < 4; c++) bb[c] = Ws[tx * 4 + c][kk];
#pragma unroll
            for (int r = 0; r < 4; r++)
#pragma unroll
                for (int c = 0; c < 4; c++) acc[r][c] = fmaf(a[r], bb[c], acc[r][c]);
        }
        __syncthreads();
    }
#pragma unroll
    for (int r = 0; r < 4; r++) {
        const int m = m0 + ty * 4 + r;
#pragma unroll
        for (int c = 0; c < 4; c++) {
            const int ng = n0 + tx * 4 + c;
            const int og = inv_gate_map(ng);
            outp[(size_t)m * G4 + ng] = acc[r][c] + bih[og] + bhh[og];
        }
    }
}

// ---------------- init (runs every launch) ----------------
__global__ void init_kernel()
{
    const int t = blockIdx.x * blockDim.x + threadIdx.x;
    if (t < 2 * 4 * NCTA * 32) ((float*)g_hp)[t] = 0.f;
    if (t < 8 * 32) g_ctr8[t] = 0u;
}

// ---------------- fast math helpers ----------------
__device__ __forceinline__ float tanh_fast(float x)
{
    float y;
    asm("tanh.approx.f32 %0, %1;" : "=f"(y) : "f"(x));
    return y;
}
__device__ __forceinline__ float sigm(float x)
{
    return fmaf(tanh_fast(0.5f * x), 0.5f, 0.5f);
}
__device__ __forceinline__ unsigned long long fma2(unsigned long long a,
                                                   unsigned long long b,
                                                   unsigned long long c)
{
    unsigned long long d;
    asm("fma.rn.f32x2 %0, %1, %2, %3;" : "=l"(d) : "l"(a), "l"(b), "l"(c));
    return d;
}
__device__ __forceinline__ unsigned long long add2(unsigned long long a,
                                                   unsigned long long b)
{
    unsigned long long d;
    asm("add.rn.f32x2 %0, %1, %2;" : "=l"(d) : "l"(a), "l"(b));
    return d;
}
__device__ __forceinline__ unsigned long long pack2(float lo, float hi)
{
    return ((unsigned long long)__float_as_uint(hi) << 32) | (unsigned long long)__float_as_uint(lo);
}
__device__ __forceinline__ const float* pre_row(unsigned u)
{
    return (u < A_DIM) ? (g_pre_enc + (size_t)u * G4)
                       : (g_pre_dec + (size_t)(u - A_DIM) * G4);
}

// ---------------- sequential recurrent kernel ----------------
__global__ void __launch_bounds__(TPB, 1) lstm_seq_kernel(
    const float* __restrict__ enc_Whh,
    const float* __restrict__ dec_Whh,
    const float* __restrict__ lin_W,
    const float* __restrict__ lin_b)
{
    __shared__ float s_h[544];   // padded h: idx(k) = k + 2*(k>>5)
    __shared__ float s_red[8];   // projection partials

    const int b    = blockIdx.x;
    const int tid  = threadIdx.x;
    const int wid  = tid >> 5;               // warps 0..3 = hidden units, 4..7 assist
    const int lane = tid & 31;
    const int gate = lane >> 3;              // 0..3 = i,f,g,o
    const int q    = lane & 7;               // 64-wide k-partition

    // compute warps (wid<4): persistent Whh rows as packed f32x2
    unsigned long long we2[32], wd2[32];
    if (wid < 4) {
        const int grow = gate * H_DIM + b * 4 + wid;
        const float2* se = (const float2*)(enc_Whh + (size_t)grow * H_DIM + 64 * q);
        const float2* sd = (const float2*)(dec_Whh + (size_t)grow * H_DIM + 64 * q);
#pragma unroll
        for (int t = 0; t < 32; t++) { float2 v = se[t]; we2[t] = pack2(v.x, v.y); }
#pragma unroll
        for (int t = 0; t < 32; t++) { float2 v = sd[t]; wd2[t] = pack2(v.x, v.y); }
    }
    // projection weights: thread covers h[2*tid], h[2*tid+1] of out dim d = b
    const float lw0 = __ldg(lin_W + b * H_DIM + 2 * tid);
    const float lw1 = __ldg(lin_W + b * H_DIM + 2 * tid + 1);
    const float lb  = __ldg(lin_b + b);

    float c_reg = 0.f;
    unsigned bar = 0;
    int buf = 0;
    float4 pre_next = (wid < 4)
        ? __ldg((const float4*)(pre_row(0) + (b << 4) + (wid << 2)))
        : make_float4(0.f, 0.f, 0.f, 0.f);
    __syncthreads();

    // read 512-wide h (parity buf, replica b&3) into padded SMEM
    auto stage = [&]() {
        if (tid < NCTA) {
            const float4 hv = __ldcg((const float4*)&g_hp[buf][b & 3][tid][0]);
            const int base = 4 * tid + 2 * (tid >> 3);
            s_h[base + 0] = hv.x;
            s_h[base + 1] = hv.y;
            s_h[base + 2] = hv.z;
            s_h[base + 3] = hv.w;
        }
        __syncthreads();
    };

    auto step = [&](const unsigned long long (&w2)[32], unsigned u) {
        const float4 pcur = pre_next;
        if (wid < 4)
            pre_next = __ldg((const float4*)(pre_row(u + 1) + (b << 4) + (wid << 2)));
        stage();
        if (wid < 4) {
            // dot over k = 64q .. 64q+63 (packed f32x2, 4 chains)
            const unsigned long long* h_lo = (const unsigned long long*)(s_h + 68 * q);
            const unsigned long long* h_hi = (const unsigned long long*)(s_h + 68 * q + 34);
            unsigned long long a0 = 0ull, a1 = 0ull, a2 = 0ull, a3 = 0ull;
#pragma unroll
            for (int t = 0; t < 16; t += 4) {
                a0 = fma2(w2[t + 0], h_lo[t + 0], a0);
                a1 = fma2(w2[t + 1], h_lo[t + 1], a1);
                a2 = fma2(w2[t + 2], h_lo[t + 2], a2);
                a3 = fma2(w2[t + 3], h_lo[t + 3], a3);
            }
#pragma unroll
            for (int t = 0; t < 16; t += 4) {
                a0 = fma2(w2[16 + t + 0], h_hi[t + 0], a0);
                a1 = fma2(w2[16 + t + 1], h_hi[t + 1], a1);
                a2 = fma2(w2[16 + t + 2], h_hi[t + 2], a2);
                a3 = fma2(w2[16 + t + 3], h_hi[t + 3], a3);
            }
            const unsigned long long at = add2(add2(a0, a1), add2(a2, a3));
            float sum = __uint_as_float((unsigned)at) + __uint_as_float((unsigned)(at >> 32));
            // reduce within each 8-lane gate group
            sum += __shfl_xor_sync(0xffffffffu, sum, 1);
            sum += __shfl_xor_sync(0xffffffffu, sum, 2);
            sum += __shfl_xor_sync(0xffffffffu, sum, 4);
            const float vi = __shfl_sync(0xffffffffu, sum, 0);
            const float vf = __shfl_sync(0xffffffffu, sum, 8);
            const float vg = __shfl_sync(0xffffffffu, sum, 16);
            const float vo = __shfl_sync(0xffffffffu, sum, 24);
            if (lane == 0) {
                const float gi = vi + pcur.x;
                const float gf = vf + pcur.y;
                const float gg = vg + pcur.z;
                const float go = vo + pcur.w;
                const float cn = fmaf(sigm(gf), c_reg, sigm(gi) * tanh_fast(gg));
                const float hn = sigm(go) * tanh_fast(cn);
                c_reg = cn;
#pragma unroll
                for (int r = 0; r < 4; r++) g_hp[buf ^ 1][r][b][wid] = hn;  // 4 replicas
            }
        }
        __syncthreads();   // h stores done before release-arrive (cumulativity handles visibility)
        bar++;
        if (tid == 0) {
            asm volatile("red.release.gpu.global.add.u32 [%0], 1;"
                         :: "l"(g_ctr8 + ((b >> 4) << 5)) : "memory");
        }
        if (tid < 8) {
            const unsigned tgt = bar * 16u;   // 16 CTAs per counter
            const unsigned int* cp = g_ctr8 + (tid << 5);
            unsigned v;
            do {
                asm volatile("ld.acquire.gpu.global.u32 %0, [%1];"
                             : "=r"(v) : "l"(cp) : "memory");
            } while (v < tgt);
        }
        __syncthreads();
        buf ^= 1;
    };

    auto proj = [&](int i) {
        stage();
        const float2 hv = *(const float2*)(s_h + 2 * tid + 2 * (tid >> 4));
        float v = fmaf(lw0, hv.x, lw1 * hv.y);
#pragma unroll
        for (int m = 16; m >= 1; m >>= 1) v += __shfl_xor_sync(0xffffffffu, v, m);
        if (lane == 0) s_red[wid] = v;
        __syncthreads();
        if (tid == 0) {
            float acc = lb;
#pragma unroll
            for (int t = 0; t < 8; t++) acc += s_red[t];
            g_outs[(NCOLS - 1 - i) * D_DIM + b] = acc;
        }
    };

    unsigned u = 0;
    // ---- encoder: 64 steps on batch row 255 only ----
    for (int t = 0; t < A_DIM; t++) step(we2, u++);
    // ---- decoder: 256 columns; projection first, then 64 steps (last column dead) ----
    for (int i = 0; i < NCOLS; i++) {
        proj(i);
        if (i < NCOLS - 1)
            for (int t = 0; t < A_DIM; t++) step(wd2, u++);
    }
}

// ---------------- broadcast outs (256x128) over leading A dim -> (64,256,128) ----------------
__global__ void bcast_kernel(float* __restrict__ out)
{
    const unsigned idx = blockIdx.x * blockDim.x + threadIdx.x;
    out[idx] = g_outs[idx & (NCOLS * D_DIM - 1)];
}

// ---------------- launch ----------------
extern "C" void kernel_launch(void* const* d_in, const int* in_sizes, int n_in,
                              void* d_out, int out_size)
{
    const float* x       = (const float*)d_in[0];
    const float* enc_Wih = (const float*)d_in[1];
    const float* enc_Whh = (const float*)d_in[2];
    const float* enc_bih = (const float*)d_in[3];
    const float* enc_bhh = (const float*)d_in[4];
    const float* dec_Wih = (const float*)d_in[5];
    const float* dec_Whh = (const float*)d_in[6];
    const float* dec_bih = (const float*)d_in[7];
    const float* dec_bhh = (const float*)d_in[8];
    const float* lin_W   = (const float*)d_in[9];
    const float* lin_b   = (const float*)d_in[10];
    float* out = (float*)d_out;

    // pre-activations (off the critical chain)
    pre_gemm_kernel<<<dim3(1, G4 / BN), TPB>>>(x, enc_Wih, enc_bih, enc_bhh, 0);
    pre_gemm_kernel<<<dim3((NCOLS * A_DIM) / BM, G4 / BN), TPB>>>(x, dec_Wih, dec_bih, dec_bhh, 1);

    // reset h lines + counters every launch (graph replays)
    init_kernel<<<128, 256>>>();

    // sequential recurrent chain: 16384 steps, persistent 128-CTA grid
    lstm_seq_kernel<<<NCTA, TPB>>>(enc_Whh, dec_Whh, lin_W, lin_b);

    // broadcast to (64, 256, 128)
    bcast_kernel<<<(64u * 256u * 128u) / 256u, 256u>>>(out);
}